// round 2
// baseline (speedup 1.0000x reference)
#include <cuda_runtime.h>

// Problem constants
static constexpr int LD  = 4;       // LOCAL_DIM
static constexpr int MD  = 64;      // M
static constexpr int TRI = 89440;   // sum_{k=1..64} k^2  (reachable (l,u,dn) tuples)

// epsilon strides (elements): shape (4, 64, 64, 65, 65) = (d, m, l, u, dn)
static constexpr unsigned long long SD = 17305600ull; // 64*64*65*65
static constexpr unsigned long long SM = 270400ull;   // 64*65*65
static constexpr unsigned long long SL = 4225ull;     // 65*65

// Scratch: transposed reachable region, layout [d][loff(l)+u*(l+1)+dn][m]
// 4 * 89440 * 64 floats = 91.6 MB (static device global: allowed, no alloc)
__device__ float g_scratch[(size_t)LD * TRI * MD];
__device__ int   g_is64;   // 1 if indices buffer is int64, 0 if int32

__device__ __host__ __forceinline__ int loff(int l) {
    return l * (l + 1) * (2 * l + 1) / 6;   // sum_{k=1..l} k^2
}

// ---------------------------------------------------------------------------
// Kernel 0: detect indices dtype. Values are in [0,4). If int64, every odd
// 32-bit word is 0. If int32, odd words are random indices (some nonzero).
// Scans 4096 32-bit words — in-bounds under either interpretation.
// ---------------------------------------------------------------------------
__global__ void detect_dtype(const unsigned* __restrict__ w) {
    __shared__ int any;
    if (threadIdx.x == 0) any = 0;
    __syncthreads();
    unsigned v = 0;
    for (int i = threadIdx.x; i < 2048; i += 256) v |= w[2 * i + 1];
    if (v) atomicOr(&any, 1);
    __syncthreads();
    if (threadIdx.x == 0) g_is64 = (any == 0) ? 1 : 0;
}

// ---------------------------------------------------------------------------
// Kernel 1: transpose eps[d, m, l, u, dn] (u<=l, dn<=l) -> scratch[d, tri, m]
// block (32,8); grid (l=64, u=64, d=4). Reads coalesced along dn, writes
// coalesced along m via a padded shared tile.
// ---------------------------------------------------------------------------
__global__ void __launch_bounds__(256) eps_transpose(const float* __restrict__ eps) {
    const int l = blockIdx.x;
    const int u = blockIdx.y;
    const int d = blockIdx.z;
    if (u > l) return;

    __shared__ float tile[64][65];   // [m][dn], padded: conflict-free both ways
    const int tx = threadIdx.x;      // 0..31
    const int ty = threadIdx.y;      // 0..7

    const size_t in0 = (size_t)d * SD + (size_t)l * SL + (size_t)u * 65ull;
    #pragma unroll
    for (int m = ty; m < 64; m += 8) {
        const size_t r = in0 + (size_t)m * SM;
        if (tx <= l)      tile[m][tx]      = eps[r + tx];
        if (tx + 32 <= l) tile[m][tx + 32] = eps[r + tx + 32];
    }
    __syncthreads();

    const size_t ob = ((size_t)d * TRI + (size_t)loff(l) + (size_t)u * (l + 1)) * 64ull;
    for (int dn = ty; dn <= l; dn += 8) {
        const size_t o = ob + (size_t)dn * 64ull;
        g_scratch[o + tx]      = tile[tx][dn];        // consecutive tx -> consecutive m
        g_scratch[o + tx + 32] = tile[tx + 32][dn];
    }
}

// ---------------------------------------------------------------------------
// Kernel 2: per batch, scan indices -> (u,dn) per site, then product over l
// of scratch rows (64 contiguous floats per (b,l)), reduce over m.
// block (64,4): x = m lane (and site index during scan), y = batch-in-block.
// ---------------------------------------------------------------------------
__global__ void __launch_bounds__(256) seggps_compute(const void* __restrict__ indices_raw,
                                                      float* __restrict__ out) {
    __shared__ int      s_scan[4][64];
    __shared__ unsigned s_base[4][64];
    __shared__ float    s_red[8];

    const int x  = threadIdx.x;   // 0..63
    const int ty = threadIdx.y;   // 0..3
    const int b  = blockIdx.x * 4 + ty;
    const size_t pos = (size_t)b * 64 + x;

    int idx;
    if (g_is64) idx = (int)((const long long*)indices_raw)[pos];
    else        idx = ((const int*)indices_raw)[pos];

    // Pack (bit0-count, bit1-count) as lo/hi bytes; Kogge-Stone inclusive scan.
    const int comb = (idx & 1) | (((idx >> 1) & 1) << 8);
    s_scan[ty][x] = comb;
    __syncthreads();
    #pragma unroll
    for (int off = 1; off < 64; off <<= 1) {
        const int vo  = s_scan[ty][x];
        const int add = (x >= off) ? s_scan[ty][x - off] : 0;
        __syncthreads();
        s_scan[ty][x] = vo + add;
        __syncthreads();
    }
    const int ex = s_scan[ty][x] - comb;   // exclusive prefix
    const int u  = ex & 0xFF;              // n_up at site x
    const int dn = ex >> 8;                // n_dn at site x

    // Base element index into scratch for (b, site=x): row of 64 m-values
    s_base[ty][x] = (unsigned)((idx * TRI + loff(x) + u * (x + 1) + dn) * 64);
    __syncthreads();

    // Product over sites: thread x = m lane; 64 coalesced 256B row reads.
    // 4-way split product to break the FMUL dependency chain.
    float p0 = 1.f, p1 = 1.f, p2 = 1.f, p3 = 1.f;
    #pragma unroll
    for (int l = 0; l < 64; l += 4) {
        p0 *= g_scratch[s_base[ty][l + 0] + x];
        p1 *= g_scratch[s_base[ty][l + 1] + x];
        p2 *= g_scratch[s_base[ty][l + 2] + x];
        p3 *= g_scratch[s_base[ty][l + 3] + x];
    }
    float prod = (p0 * p1) * (p2 * p3);

    // Sum over m: shuffle-reduce within each warp, combine 2 warps per batch
    #pragma unroll
    for (int o = 16; o > 0; o >>= 1)
        prod += __shfl_xor_sync(0xffffffffu, prod, o);
    const int warp = (ty * 64 + x) >> 5;   // 0..7
    if ((x & 31) == 0) s_red[warp] = prod;
    __syncthreads();
    if (x == 0) out[b] = s_red[ty * 2] + s_red[ty * 2 + 1];
}

// ---------------------------------------------------------------------------
extern "C" void kernel_launch(void* const* d_in, const int* in_sizes, int n_in,
                              void* d_out, int out_size) {
    const unsigned* indices_w = (const unsigned*)d_in[0];
    const float*    eps       = (const float*)d_in[1];
    float*          out       = (float*)d_out;

    detect_dtype<<<1, 256>>>(indices_w);
    eps_transpose<<<dim3(64, 64, 4), dim3(32, 8)>>>(eps);
    seggps_compute<<<8192 / 4, dim3(64, 4)>>>(d_in[0], out);
}

// round 5
// speedup vs baseline: 1.5307x; 1.5307x over previous
#include <cuda_runtime.h>

// Problem constants
static constexpr int LD  = 4;       // LOCAL_DIM
static constexpr int MD  = 64;      // M
static constexpr int TRI = 89440;   // sum_{k=1..64} k^2  (reachable (l,u,dn) tuples)

// epsilon strides (elements): shape (4, 64, 64, 65, 65) = (d, m, l, u, dn)
static constexpr unsigned long long SD = 17305600ull; // 64*64*65*65
static constexpr unsigned long long SM = 270400ull;   // 64*65*65
static constexpr unsigned long long SL = 4225ull;     // 65*65

// Scratch: transposed reachable region, layout [d][loff(l)+u*(l+1)+dn][m]
__device__ float g_scratch[(size_t)LD * TRI * MD];
// Realized-tuple mask: per (d, l*(l+1)/2 + u), bit dn set if tuple realized.
__device__ unsigned long long g_tmask[LD][2080];

__device__ __host__ __forceinline__ int loff(int l) {
    return l * (l + 1) * (2 * l + 1) / 6;   // sum_{k=1..l} k^2
}

// Per-warp dtype detection: words 1,3,..,63 of the indices buffer are all zero
// iff the buffer is int64 (values < 4). Always in-bounds under either dtype.
__device__ __forceinline__ bool detect_is64(const void* raw, int lane) {
    unsigned wodd = ((const unsigned*)raw)[2 * lane + 1];
    return __ballot_sync(0xffffffffu, wodd != 0u) == 0u;
}

// Load index value for flat position pos under detected dtype.
__device__ __forceinline__ int load_idx(const void* raw, size_t pos, bool is64) {
    if (is64) return (int)((const long long*)raw)[pos];
    return ((const int*)raw)[pos];
}

// ---------------------------------------------------------------------------
// Kernel 1: mark realized (d, l, u, dn) tuples. block (64,4): x=site, ty=batch.
// Ballot-based prefix counts, then one spread global atomicOr per thread.
// ---------------------------------------------------------------------------
__global__ void __launch_bounds__(256) mark_tuples(const void* __restrict__ raw) {
    const int x  = threadIdx.x;            // site 0..63
    const int ty = threadIdx.y;            // batch-in-block
    const int b  = blockIdx.x * 4 + ty;
    const int lane = (ty * 64 + x) & 31;

    const bool is64 = detect_is64(raw, lane);
    const int idx = load_idx(raw, (size_t)b * 64 + x, is64);

    const unsigned m0 = __ballot_sync(0xffffffffu, idx & 1);
    const unsigned m1 = __ballot_sync(0xffffffffu, idx & 2);
    __shared__ unsigned s0[4][2], s1[4][2];
    const int half = x >> 5;
    if ((x & 31) == 0) { s0[ty][half] = m0; s1[ty][half] = m1; }
    __syncthreads();
    const unsigned lm = (1u << (x & 31)) - 1u;
    const int u  = __popc(m0 & lm) + (half ? __popc(s0[ty][0]) : 0);
    const int dn = __popc(m1 & lm) + (half ? __popc(s1[ty][0]) : 0);

    atomicOr(&g_tmask[idx][x * (x + 1) / 2 + u], 1ull << dn);
}

// ---------------------------------------------------------------------------
// Kernel 2: transpose eps[d, m, l, u, dn] -> scratch[d, tri, m], but ONLY the
// realized (d,l,u) rows, and only the realized dn band within each row.
// block (32,8); grid (l=64, u=64, d=4).
// ---------------------------------------------------------------------------
__global__ void __launch_bounds__(256) eps_transpose(const float* __restrict__ eps) {
    const int l = blockIdx.x;
    const int u = blockIdx.y;
    const int d = blockIdx.z;
    if (u > l) return;
    const unsigned long long mask = g_tmask[d][l * (l + 1) / 2 + u];
    if (mask == 0ull) return;
    const int dn0 = __ffsll((long long)mask) - 1;   // first realized dn
    const int dn1 = 63 - __clzll((long long)mask);  // last realized dn
    const int W   = dn1 - dn0;                      // band width - 1

    __shared__ float tile[64][65];   // [m][dn-dn0], padded: conflict-free
    const int tx = threadIdx.x;      // 0..31
    const int ty = threadIdx.y;      // 0..7

    const size_t in0 = (size_t)d * SD + (size_t)l * SL + (size_t)u * 65ull + dn0;
    #pragma unroll
    for (int m = ty; m < 64; m += 8) {
        const size_t r = in0 + (size_t)m * SM;
        if (tx <= W)      tile[m][tx]      = eps[r + tx];
        if (tx + 32 <= W) tile[m][tx + 32] = eps[r + tx + 32];
    }
    __syncthreads();

    const size_t ob = ((size_t)d * TRI + (size_t)loff(l) + (size_t)u * (l + 1)) * 64ull;
    for (int dn = dn0 + ty; dn <= dn1; dn += 8) {
        const size_t o = ob + (size_t)dn * 64ull;
        const int c = dn - dn0;
        g_scratch[o + tx]      = tile[tx][c];        // consecutive tx -> consecutive m
        g_scratch[o + tx + 32] = tile[tx + 32][c];
    }
}

// ---------------------------------------------------------------------------
// Kernel 3: per batch, ballot-prefix -> (u,dn) per site, product over 64
// coalesced scratch rows, reduce over m. block (64,4): x = m lane, ty = batch.
// ---------------------------------------------------------------------------
__global__ void __launch_bounds__(256) seggps_compute(const void* __restrict__ raw,
                                                      float* __restrict__ out) {
    __shared__ unsigned s_base[4][64];
    __shared__ unsigned s0[4][2], s1[4][2];
    __shared__ float    s_red[8];

    const int x  = threadIdx.x;   // 0..63 (site during scan, m lane during product)
    const int ty = threadIdx.y;   // 0..3
    const int b  = blockIdx.x * 4 + ty;
    const int lane = (ty * 64 + x) & 31;

    const bool is64 = detect_is64(raw, lane);
    const int idx = load_idx(raw, (size_t)b * 64 + x, is64);

    const unsigned m0 = __ballot_sync(0xffffffffu, idx & 1);
    const unsigned m1 = __ballot_sync(0xffffffffu, idx & 2);
    const int half = x >> 5;
    if ((x & 31) == 0) { s0[ty][half] = m0; s1[ty][half] = m1; }
    __syncthreads();
    const unsigned lm = (1u << (x & 31)) - 1u;
    const int u  = __popc(m0 & lm) + (half ? __popc(s0[ty][0]) : 0);
    const int dn = __popc(m1 & lm) + (half ? __popc(s1[ty][0]) : 0);

    s_base[ty][x] = (unsigned)((idx * TRI + loff(x) + u * (x + 1) + dn) * 64);
    __syncthreads();

    // Product over sites: thread x = m lane; 64 coalesced 256B row reads.
    // 8 accumulators -> MLP 8 against L2 latency.
    float p0 = 1.f, p1 = 1.f, p2 = 1.f, p3 = 1.f;
    float p4 = 1.f, p5 = 1.f, p6 = 1.f, p7 = 1.f;
    #pragma unroll
    for (int l = 0; l < 64; l += 8) {
        p0 *= g_scratch[s_base[ty][l + 0] + x];
        p1 *= g_scratch[s_base[ty][l + 1] + x];
        p2 *= g_scratch[s_base[ty][l + 2] + x];
        p3 *= g_scratch[s_base[ty][l + 3] + x];
        p4 *= g_scratch[s_base[ty][l + 4] + x];
        p5 *= g_scratch[s_base[ty][l + 5] + x];
        p6 *= g_scratch[s_base[ty][l + 6] + x];
        p7 *= g_scratch[s_base[ty][l + 7] + x];
    }
    float prod = ((p0 * p1) * (p2 * p3)) * ((p4 * p5) * (p6 * p7));

    // Sum over m: shuffle-reduce within each warp, combine 2 warps per batch
    #pragma unroll
    for (int o = 16; o > 0; o >>= 1)
        prod += __shfl_xor_sync(0xffffffffu, prod, o);
    const int warp = (ty * 64 + x) >> 5;   // 0..7
    if ((x & 31) == 0) s_red[warp] = prod;
    __syncthreads();
    if (x == 0) out[b] = s_red[ty * 2] + s_red[ty * 2 + 1];
}

// ---------------------------------------------------------------------------
extern "C" void kernel_launch(void* const* d_in, const int* in_sizes, int n_in,
                              void* d_out, int out_size) {
    const float* eps = (const float*)d_in[1];
    float*       out = (float*)d_out;

    mark_tuples  <<<8192 / 4, dim3(64, 4)>>>(d_in[0]);
    eps_transpose<<<dim3(64, 64, 4), dim3(32, 8)>>>(eps);
    seggps_compute<<<8192 / 4, dim3(64, 4)>>>(d_in[0], out);
}